// round 3
// baseline (speedup 1.0000x reference)
#include <cuda_runtime.h>
#include <mma.h>
#include <cstdint>

using namespace nvcuda;

#define B_ 4096
#define H_ 1024
#define E_ 1024
#define V_ 32000

// Scratch (device-global arrays: allocation-free per harness rules)
__device__ float g_zf[(size_t)B_ * H_];
__device__ float g_zi[(size_t)B_ * H_];
__device__ float g_zc[(size_t)B_ * H_];
__device__ float g_zo[(size_t)B_ * H_];
__device__ float g_ct[(size_t)B_ * H_];
__device__ float g_ht[(size_t)B_ * H_];

constexpr int BM = 128, BN = 128, BK = 32;
constexpr int APAD = 8, BPAD = 8;
constexpr int A_ROW = BK + APAD;          // 40 floats
constexpr int B_ROW = BN + BPAD;          // 136 floats
constexpr int A_STAGE = BM * A_ROW;       // 5120 floats
constexpr int B_STAGE = BK * B_ROW;       // 4352 floats
constexpr int SMEM_FLOATS = 2 * (A_STAGE + B_STAGE);
constexpr int SMEM_BYTES = SMEM_FLOATS * 4;   // 75776

__device__ __forceinline__ float sigmoidf_(float x) {
    return 1.0f / (1.0f + expf(-x));
}

__device__ __forceinline__ void cp_async16(uint32_t dst, const void* src) {
    asm volatile("cp.async.cg.shared.global [%0], [%1], 16;\n" :: "r"(dst), "l"(src));
}
__device__ __forceinline__ void cp_commit() {
    asm volatile("cp.async.commit_group;\n" ::: "memory");
}
template <int N>
__device__ __forceinline__ void cp_wait() {
    asm volatile("cp.async.wait_group %0;\n" :: "n"(N) : "memory");
}

// C = epilogue( sum_p A_p @ W_p  [+ C if MODE==1] )
// MODE: 0 = store, 1 = accumulate onto existing C, 2 = sigmoid(store)
// cp.async double-buffered; NPAIR*K/BK stages flattened (no drain between pairs).
template <int MODE, int NPAIR>
__global__ __launch_bounds__(256) void gemm_tf32(
    const float* __restrict__ A0, const float* __restrict__ W0,
    const float* __restrict__ A1, const float* __restrict__ W1,
    const float* __restrict__ A2, const float* __restrict__ W2,
    float* __restrict__ C, int M, int N, int K)
{
    extern __shared__ __align__(16) float smem[];
    float* As = smem;                 // [2][BM][A_ROW]
    float* Bs = smem + 2 * A_STAGE;   // [2][BK][B_ROW]

    const int tid    = threadIdx.x;
    const int wid    = tid >> 5;
    const int warp_m = wid & 3;        // 4 warps along M (32 rows each)
    const int warp_n = wid >> 2;       // 2 warps along N (64 cols each)
    const int bm     = blockIdx.y * BM;
    const int bn     = blockIdx.x * BN;

    const uint32_t sbase = (uint32_t)__cvta_generic_to_shared(smem);

    wmma::fragment<wmma::accumulator, 16, 16, 8, float> acc[2][4];

    #pragma unroll
    for (int i = 0; i < 2; i++) {
        #pragma unroll
        for (int j = 0; j < 4; j++) {
            if (MODE == 1) {
                const float* cp = C + (size_t)(bm + warp_m * 32 + i * 16) * N
                                    + (bn + warp_n * 64 + j * 16);
                wmma::load_matrix_sync(acc[i][j], cp, N, wmma::mem_row_major);
            } else {
                wmma::fill_fragment(acc[i][j], 0.0f);
            }
        }
    }

    const float* Aps[3] = {A0, A1, A2};
    const float* Wps[3] = {W0, W1, W2};

    const int KSTAGES = K / BK;
    const int NS = NPAIR * KSTAGES;

    // Per-thread load coordinates (fixed across stages)
    const int ar = tid >> 3;             // 0..31  A row base
    const int ac = (tid & 7) * 4;        // 0..28  A col (floats)
    const int br = tid >> 5;             // 0..7   B row base
    const int bc = (tid & 31) * 4;       // 0..124 B col (floats)

    auto load_stage = [&](int buf, int s) {
        const int p  = s / KSTAGES;
        const int k0 = (s - p * KSTAGES) * BK;
        const float* __restrict__ A = Aps[p];
        const float* __restrict__ W = Wps[p];
        // A tile: [BM x BK] -> As[buf]
        #pragma unroll
        for (int rr = 0; rr < 4; rr++) {
            uint32_t dst = sbase + (uint32_t)(buf * A_STAGE + (ar + rr * 32) * A_ROW + ac) * 4u;
            const float* src = A + (size_t)(bm + ar + rr * 32) * K + k0 + ac;
            cp_async16(dst, src);
        }
        // B tile: [BK x BN] -> Bs[buf]
        #pragma unroll
        for (int rr = 0; rr < 4; rr++) {
            uint32_t dst = sbase + (uint32_t)(2 * A_STAGE + buf * B_STAGE + (br + rr * 8) * B_ROW + bc) * 4u;
            const float* src = W + (size_t)(k0 + br + rr * 8) * N + bn + bc;
            cp_async16(dst, src);
        }
    };

    // Prefetch stage 0 into buffer 0
    load_stage(0, 0);
    cp_commit();

    #pragma unroll 1
    for (int s = 0; s < NS; s++) {
        const int buf = s & 1;
        if (s + 1 < NS) {
            load_stage(buf ^ 1, s + 1);
            cp_commit();
            cp_wait<1>();
        } else {
            cp_wait<0>();
        }
        __syncthreads();

        const float* Ab = As + buf * A_STAGE;
        const float* Bb = Bs + 2 * A_STAGE * 0 + buf * B_STAGE;  // offset applied below via Bs
        const float* Bbase = Bs + buf * B_STAGE;

        #pragma unroll
        for (int kk = 0; kk < BK; kk += 8) {
            wmma::fragment<wmma::matrix_a, 16, 16, 8, wmma::precision::tf32, wmma::row_major> af[2];
            wmma::fragment<wmma::matrix_b, 16, 16, 8, wmma::precision::tf32, wmma::row_major> bf[4];

            #pragma unroll
            for (int i = 0; i < 2; i++) {
                wmma::load_matrix_sync(af[i], Ab + (warp_m * 32 + i * 16) * A_ROW + kk, A_ROW);
                #pragma unroll
                for (int t = 0; t < af[i].num_elements; t++)
                    af[i].x[t] = wmma::__float_to_tf32(af[i].x[t]);
            }
            #pragma unroll
            for (int j = 0; j < 4; j++) {
                wmma::load_matrix_sync(bf[j], Bbase + kk * B_ROW + warp_n * 64 + j * 16, B_ROW);
                #pragma unroll
                for (int t = 0; t < bf[j].num_elements; t++)
                    bf[j].x[t] = wmma::__float_to_tf32(bf[j].x[t]);
            }
            #pragma unroll
            for (int i = 0; i < 2; i++)
                #pragma unroll
                for (int j = 0; j < 4; j++)
                    wmma::mma_sync(acc[i][j], af[i], bf[j], acc[i][j]);
        }
        __syncthreads();
        (void)Bb;
    }

    // --- epilogue ---
    #pragma unroll
    for (int i = 0; i < 2; i++) {
        #pragma unroll
        for (int j = 0; j < 4; j++) {
            if (MODE == 2) {
                #pragma unroll
                for (int t = 0; t < acc[i][j].num_elements; t++)
                    acc[i][j].x[t] = sigmoidf_(acc[i][j].x[t]);
            }
            float* cp = C + (size_t)(bm + warp_m * 32 + i * 16) * N
                          + (bn + warp_n * 64 + j * 16);
            wmma::store_matrix_sync(cp, acc[i][j], N, wmma::mem_row_major);
        }
    }
}

// Ct = sigmoid(zf)*c + sigmoid(zi)*tanh(zc)
__global__ void lstm_ew1(const float* __restrict__ zf, const float* __restrict__ zi,
                         const float* __restrict__ zc, const float* __restrict__ c,
                         float* __restrict__ ct, int n)
{
    int i = blockIdx.x * blockDim.x + threadIdx.x;
    if (i < n) {
        float Ft = sigmoidf_(zf[i]);
        float It = sigmoidf_(zi[i]);
        float Cd = tanhf(zc[i]);
        ct[i] = Ft * c[i] + It * Cd;
    }
}

// Ht = sigmoid(zo)*tanh(Ct)
__global__ void lstm_ew2(const float* __restrict__ zo, const float* __restrict__ ct,
                         float* __restrict__ ht, int n)
{
    int i = blockIdx.x * blockDim.x + threadIdx.x;
    if (i < n) {
        float Ot = sigmoidf_(zo[i]);
        ht[i] = Ot * tanhf(ct[i]);
    }
}

extern "C" void kernel_launch(void* const* d_in, const int* in_sizes, int n_in,
                              void* d_out, int out_size)
{
    const float* x          = (const float*)d_in[0];
    const float* h          = (const float*)d_in[1];
    const float* c          = (const float*)d_in[2];
    const float* w_forget   = (const float*)d_in[3];
    const float* w_input    = (const float*)d_in[4];
    const float* w_output   = (const float*)d_in[5];
    const float* w_c_dash   = (const float*)d_in[6];
    const float* w_forget_c = (const float*)d_in[7];
    const float* w_input_c  = (const float*)d_in[8];
    const float* w_output_c = (const float*)d_in[9];
    const float* w_op       = (const float*)d_in[10];
    const float* w_ip_f     = (const float*)d_in[11];
    const float* w_ip_i     = (const float*)d_in[12];
    const float* w_ip_o     = (const float*)d_in[13];
    const float* w_ip_c     = (const float*)d_in[14];
    float* out = (float*)d_out;

    // Allow 74KB dynamic smem on every instantiation (cheap, idempotent,
    // graph-capture-safe: not a stream operation).
    cudaFuncSetAttribute((const void*)gemm_tf32<0, 3>, cudaFuncAttributeMaxDynamicSharedMemorySize, SMEM_BYTES);
    cudaFuncSetAttribute((const void*)gemm_tf32<0, 2>, cudaFuncAttributeMaxDynamicSharedMemorySize, SMEM_BYTES);
    cudaFuncSetAttribute((const void*)gemm_tf32<1, 1>, cudaFuncAttributeMaxDynamicSharedMemorySize, SMEM_BYTES);
    cudaFuncSetAttribute((const void*)gemm_tf32<2, 1>, cudaFuncAttributeMaxDynamicSharedMemorySize, SMEM_BYTES);

    float *zf, *zi, *zc, *zo, *ctbuf, *htbuf;
    cudaGetSymbolAddress((void**)&zf, g_zf);
    cudaGetSymbolAddress((void**)&zi, g_zi);
    cudaGetSymbolAddress((void**)&zc, g_zc);
    cudaGetSymbolAddress((void**)&zo, g_zo);
    cudaGetSymbolAddress((void**)&ctbuf, g_ct);
    cudaGetSymbolAddress((void**)&htbuf, g_ht);

    const size_t BV = (size_t)B_ * V_;
    const size_t BH = (size_t)B_ * H_;

    float* ht_out = ((size_t)out_size >= BV + 2 * BH) ? (out + BV)      : htbuf;
    float* ct_out = ((size_t)out_size >= BV + 2 * BH) ? (out + BV + BH) : ctbuf;

    dim3 blk(256);
    dim3 g_h(H_ / BN, B_ / BM);     // (8, 32)
    dim3 g_v(V_ / BN, B_ / BM);     // (250, 32)

    // Gate pre-activations
    gemm_tf32<0, 3><<<g_h, blk, SMEM_BYTES>>>(x, w_ip_f, h, w_forget, c, w_forget_c, zf, B_, H_, 1024);
    gemm_tf32<0, 3><<<g_h, blk, SMEM_BYTES>>>(x, w_ip_i, h, w_input,  c, w_input_c,  zi, B_, H_, 1024);
    gemm_tf32<0, 2><<<g_h, blk, SMEM_BYTES>>>(x, w_ip_c, h, w_c_dash, nullptr, nullptr, zc, B_, H_, 1024);
    gemm_tf32<0, 2><<<g_h, blk, SMEM_BYTES>>>(x, w_ip_o, h, w_output, nullptr, nullptr, zo, B_, H_, 1024);

    // Ct
    lstm_ew1<<<(unsigned)(BH / 256), blk>>>(zf, zi, zc, c, ct_out, (int)BH);

    // zo += Ct @ w_output_c
    gemm_tf32<1, 1><<<g_h, blk, SMEM_BYTES>>>(ct_out, w_output_c, nullptr, nullptr, nullptr, nullptr,
                                              zo, B_, H_, H_);

    // Ht
    lstm_ew2<<<(unsigned)(BH / 256), blk>>>(zo, ct_out, ht_out, (int)BH);

    // Yt = sigmoid(Ht @ w_op)
    gemm_tf32<2, 1><<<g_v, blk, SMEM_BYTES>>>(ht_out, w_op, nullptr, nullptr, nullptr, nullptr,
                                              out, B_, V_, H_);
}

// round 5
// speedup vs baseline: 1.2583x; 1.2583x over previous
#include <cuda_runtime.h>
#include <mma.h>
#include <cstdint>

using namespace nvcuda;

#define B_ 4096
#define H_ 1024
#define V_ 32000

// Scratch (device-global arrays: allocation-free per harness rules)
__device__ float g_zf[(size_t)B_ * H_];
__device__ float g_zi[(size_t)B_ * H_];
__device__ float g_zc[(size_t)B_ * H_];
__device__ float g_zo[(size_t)B_ * H_];
__device__ float g_ct[(size_t)B_ * H_];
__device__ float g_ht[(size_t)B_ * H_];

constexpr int BM = 128, BN = 128, BK = 32;
constexpr int APAD = 8, BPAD = 8;
constexpr int A_ROW = BK + APAD;          // 40 floats
constexpr int B_ROW = BN + BPAD;          // 136 floats
constexpr int A_STAGE = BM * A_ROW;       // 5120 floats
constexpr int B_STAGE = BK * B_ROW;       // 4352 floats
constexpr int SMEM_FLOATS = 2 * (A_STAGE + B_STAGE);
constexpr int SMEM_BYTES = SMEM_FLOATS * 4;   // 75776

__device__ __forceinline__ float sigmoidf_(float x) {
    return 1.0f / (1.0f + expf(-x));
}

__device__ __forceinline__ void cp_async16(uint32_t dst, const void* src) {
    asm volatile("cp.async.cg.shared.global [%0], [%1], 16;\n" :: "r"(dst), "l"(src));
}
__device__ __forceinline__ void cp_commit() {
    asm volatile("cp.async.commit_group;\n" ::: "memory");
}
template <int N>
__device__ __forceinline__ void cp_wait() {
    asm volatile("cp.async.wait_group %0;\n" :: "n"(N) : "memory");
}

// ======================= pipelined body (cp.async, dbl-buffer) =======================
// For latency-bound launches (gates, peephole). K per pair fixed at 1024.
// MODE: 0 = store, 1 = accumulate onto existing C.
template <int MODE>
__device__ __forceinline__ void pipe_gemm_body(
    const float* const* Aps, const float* const* Wps, int npair,
    float* __restrict__ C, int bm, int bn, int N)
{
    extern __shared__ __align__(16) float smem[];
    float* As = smem;                 // [2][BM][A_ROW]
    float* Bs = smem + 2 * A_STAGE;   // [2][BK][B_ROW]

    const int tid    = threadIdx.x;
    const int wid    = tid >> 5;
    const int warp_m = wid & 3;
    const int warp_n = wid >> 2;

    const uint32_t sbase = (uint32_t)__cvta_generic_to_shared(smem);

    wmma::fragment<wmma::accumulator, 16, 16, 8, float> acc[2][4];
    #pragma unroll
    for (int i = 0; i < 2; i++)
        #pragma unroll
        for (int j = 0; j < 4; j++) {
            if (MODE == 1) {
                const float* cp = C + (size_t)(bm + warp_m * 32 + i * 16) * N
                                    + (bn + warp_n * 64 + j * 16);
                wmma::load_matrix_sync(acc[i][j], cp, N, wmma::mem_row_major);
            } else {
                wmma::fill_fragment(acc[i][j], 0.0f);
            }
        }

    const int NS = npair * 32;   // K=1024 per pair, BK=32

    const int ar = tid >> 3;             // 0..31
    const int ac = (tid & 7) * 4;        // 0..28
    const int br = tid >> 5;             // 0..7
    const int bc = (tid & 31) * 4;       // 0..124

    auto load_stage = [&](int buf, int s) {
        const int p  = s >> 5;
        const int k0 = (s & 31) * BK;
        const float* __restrict__ A = Aps[p];
        const float* __restrict__ W = Wps[p];
        #pragma unroll
        for (int rr = 0; rr < 4; rr++) {
            uint32_t dst = sbase + (uint32_t)(buf * A_STAGE + (ar + rr * 32) * A_ROW + ac) * 4u;
            cp_async16(dst, A + (size_t)(bm + ar + rr * 32) * 1024 + k0 + ac);
        }
        #pragma unroll
        for (int rr = 0; rr < 4; rr++) {
            uint32_t dst = sbase + (uint32_t)(2 * A_STAGE + buf * B_STAGE + (br + rr * 8) * B_ROW + bc) * 4u;
            cp_async16(dst, W + (size_t)(k0 + br + rr * 8) * N + bn + bc);
        }
    };

    load_stage(0, 0);
    cp_commit();

    #pragma unroll 1
    for (int s = 0; s < NS; s++) {
        const int buf = s & 1;
        if (s + 1 < NS) {
            load_stage(buf ^ 1, s + 1);
            cp_commit();
            cp_wait<1>();
        } else {
            cp_wait<0>();
        }
        __syncthreads();

        const float* Ab    = As + buf * A_STAGE;
        const float* Bbase = Bs + buf * B_STAGE;

        #pragma unroll
        for (int kk = 0; kk < BK; kk += 8) {
            wmma::fragment<wmma::matrix_a, 16, 16, 8, wmma::precision::tf32, wmma::row_major> af[2];
            wmma::fragment<wmma::matrix_b, 16, 16, 8, wmma::precision::tf32, wmma::row_major> bf[4];
            #pragma unroll
            for (int i = 0; i < 2; i++) {
                wmma::load_matrix_sync(af[i], Ab + (warp_m * 32 + i * 16) * A_ROW + kk, A_ROW);
                #pragma unroll
                for (int t = 0; t < af[i].num_elements; t++)
                    af[i].x[t] = wmma::__float_to_tf32(af[i].x[t]);
            }
            #pragma unroll
            for (int j = 0; j < 4; j++) {
                wmma::load_matrix_sync(bf[j], Bbase + kk * B_ROW + warp_n * 64 + j * 16, B_ROW);
                #pragma unroll
                for (int t = 0; t < bf[j].num_elements; t++)
                    bf[j].x[t] = wmma::__float_to_tf32(bf[j].x[t]);
            }
            #pragma unroll
            for (int i = 0; i < 2; i++)
                #pragma unroll
                for (int j = 0; j < 4; j++)
                    wmma::mma_sync(acc[i][j], af[i], bf[j], acc[i][j]);
        }
        __syncthreads();
    }

    #pragma unroll
    for (int i = 0; i < 2; i++)
        #pragma unroll
        for (int j = 0; j < 4; j++) {
            float* cp = C + (size_t)(bm + warp_m * 32 + i * 16) * N
                          + (bn + warp_n * 64 + j * 16);
            wmma::store_matrix_sync(cp, acc[i][j], N, wmma::mem_row_major);
        }
}

// Fused 4-gate kernel: grid (32, 32); x = gate*8 + nblock, y = m-block.
__global__ __launch_bounds__(256) void gates_kernel(
    const float* x, const float* h, const float* c,
    const float* wf, const float* wi, const float* wc, const float* wo,
    const float* uf, const float* ui, const float* uc, const float* uo,
    const float* pf, const float* pi,
    float* zf, float* zi, float* zc, float* zo)
{
    const int gate = blockIdx.x >> 3;
    const int bn   = (blockIdx.x & 7) * 128;
    const int bm   = blockIdx.y * 128;
    const float* Ap[3]; const float* Bp[3]; int np = 2; float* C;
    Ap[0] = x; Ap[1] = h; Ap[2] = c;
    switch (gate) {
        case 0:  Bp[0] = uf; Bp[1] = wf; Bp[2] = pf; np = 3; C = g_zf; break;
        case 1:  Bp[0] = ui; Bp[1] = wi; Bp[2] = pi; np = 3; C = g_zi; break;
        case 2:  Bp[0] = uc; Bp[1] = wc; C = g_zc; break;
        default: Bp[0] = uo; Bp[1] = wo; C = g_zo; break;
    }
    pipe_gemm_body<0>(Ap, Bp, np, C, bm, bn, 1024);
}

// Peephole accumulate: zo += Ct @ w_output_c. grid (8, 32).
__global__ __launch_bounds__(256) void peephole_kernel(
    const float* ct, const float* w, float* zo)
{
    const float* Ap[1] = {ct}; const float* Bp[1] = {w};
    pipe_gemm_body<1>(Ap, Bp, 1, zo, blockIdx.y * 128, blockIdx.x * 128, 1024);
}

// ======================= simple body (measured 81 TF/s on vocab) =======================
// Yt = sigmoid(Ht @ w_op). K = 1024, N = 32000. grid (250, 32).
__global__ __launch_bounds__(256) void vocab_kernel(
    const float* __restrict__ A, const float* __restrict__ W,
    float* __restrict__ C, int N)
{
    __shared__ __align__(16) float As[BM][A_ROW];
    __shared__ __align__(16) float Bs[BK][B_ROW];

    const int tid    = threadIdx.x;
    const int wid    = tid >> 5;
    const int warp_m = wid & 3;
    const int warp_n = wid >> 2;
    const int bm     = blockIdx.y * BM;
    const int bn     = blockIdx.x * BN;

    wmma::fragment<wmma::accumulator, 16, 16, 8, float> acc[2][4];
    #pragma unroll
    for (int i = 0; i < 2; i++)
        #pragma unroll
        for (int j = 0; j < 4; j++)
            wmma::fill_fragment(acc[i][j], 0.0f);

    #pragma unroll 1
    for (int k0 = 0; k0 < 1024; k0 += BK) {
        {
            const int r = tid >> 3;
            const int cc = (tid & 7) * 4;
            #pragma unroll
            for (int rr = 0; rr < 4; rr++) {
                float4 v = *(const float4*)(A + (size_t)(bm + r + rr * 32) * 1024 + k0 + cc);
                *(float4*)&As[r + rr * 32][cc] = v;
            }
        }
        {
            const int r = tid >> 5;
            const int cc = (tid & 31) * 4;
            #pragma unroll
            for (int rr = 0; rr < 4; rr++) {
                float4 v = *(const float4*)(W + (size_t)(k0 + r + rr * 8) * N + bn + cc);
                *(float4*)&Bs[r + rr * 8][cc] = v;
            }
        }
        __syncthreads();

        #pragma unroll
        for (int kk = 0; kk < BK; kk += 8) {
            wmma::fragment<wmma::matrix_a, 16, 16, 8, wmma::precision::tf32, wmma::row_major> af[2];
            wmma::fragment<wmma::matrix_b, 16, 16, 8, wmma::precision::tf32, wmma::row_major> bf[4];
            #pragma unroll
            for (int i = 0; i < 2; i++) {
                wmma::load_matrix_sync(af[i], &As[warp_m * 32 + i * 16][kk], A_ROW);
                #pragma unroll
                for (int t = 0; t < af[i].num_elements; t++)
                    af[i].x[t] = wmma::__float_to_tf32(af[i].x[t]);
            }
            #pragma unroll
            for (int j = 0; j < 4; j++) {
                wmma::load_matrix_sync(bf[j], &Bs[kk][warp_n * 64 + j * 16], B_ROW);
                #pragma unroll
                for (int t = 0; t < bf[j].num_elements; t++)
                    bf[j].x[t] = wmma::__float_to_tf32(bf[j].x[t]);
            }
            #pragma unroll
            for (int i = 0; i < 2; i++)
                #pragma unroll
                for (int j = 0; j < 4; j++)
                    wmma::mma_sync(acc[i][j], af[i], bf[j], acc[i][j]);
        }
        __syncthreads();
    }

    #pragma unroll
    for (int i = 0; i < 2; i++)
        #pragma unroll
        for (int j = 0; j < 4; j++) {
            #pragma unroll
            for (int t = 0; t < acc[i][j].num_elements; t++)
                acc[i][j].x[t] = sigmoidf_(acc[i][j].x[t]);
            float* cp = C + (size_t)(bm + warp_m * 32 + i * 16) * N
                          + (bn + warp_n * 64 + j * 16);
            wmma::store_matrix_sync(cp, acc[i][j], N, wmma::mem_row_major);
        }
}

// ======================= elementwise =======================
__global__ void lstm_ew1(const float* __restrict__ zf, const float* __restrict__ zi,
                         const float* __restrict__ zc, const float* __restrict__ c,
                         float* __restrict__ ct, int n)
{
    int i = blockIdx.x * blockDim.x + threadIdx.x;
    if (i < n)
        ct[i] = sigmoidf_(zf[i]) * c[i] + sigmoidf_(zi[i]) * tanhf(zc[i]);
}
__global__ void lstm_ew2(const float* __restrict__ zo, const float* __restrict__ ct,
                         float* __restrict__ ht, int n)
{
    int i = blockIdx.x * blockDim.x + threadIdx.x;
    if (i < n)
        ht[i] = sigmoidf_(zo[i]) * tanhf(ct[i]);
}

extern "C" void kernel_launch(void* const* d_in, const int* in_sizes, int n_in,
                              void* d_out, int out_size)
{
    const float* x          = (const float*)d_in[0];
    const float* h          = (const float*)d_in[1];
    const float* c          = (const float*)d_in[2];
    const float* w_forget   = (const float*)d_in[3];
    const float* w_input    = (const float*)d_in[4];
    const float* w_output   = (const float*)d_in[5];
    const float* w_c_dash   = (const float*)d_in[6];
    const float* w_forget_c = (const float*)d_in[7];
    const float* w_input_c  = (const float*)d_in[8];
    const float* w_output_c = (const float*)d_in[9];
    const float* w_op       = (const float*)d_in[10];
    const float* w_ip_f     = (const float*)d_in[11];
    const float* w_ip_i     = (const float*)d_in[12];
    const float* w_ip_o     = (const float*)d_in[13];
    const float* w_ip_c     = (const float*)d_in[14];
    float* out = (float*)d_out;

    cudaFuncSetAttribute((const void*)gates_kernel,    cudaFuncAttributeMaxDynamicSharedMemorySize, SMEM_BYTES);
    cudaFuncSetAttribute((const void*)peephole_kernel, cudaFuncAttributeMaxDynamicSharedMemorySize, SMEM_BYTES);

    float *zf, *zi, *zc, *zo, *ctbuf, *htbuf;
    cudaGetSymbolAddress((void**)&zf, g_zf);
    cudaGetSymbolAddress((void**)&zi, g_zi);
    cudaGetSymbolAddress((void**)&zc, g_zc);
    cudaGetSymbolAddress((void**)&zo, g_zo);
    cudaGetSymbolAddress((void**)&ctbuf, g_ct);
    cudaGetSymbolAddress((void**)&htbuf, g_ht);

    const size_t BV = (size_t)B_ * V_;
    const size_t BH = (size_t)B_ * H_;
    float* ht_out = ((size_t)out_size >= BV + 2 * BH) ? (out + BV)      : htbuf;
    float* ct_out = ((size_t)out_size >= BV + 2 * BH) ? (out + BV + BH) : ctbuf;

    dim3 blk(256);

    // All 4 gate pre-activations in one launch (1024 CTAs)
    gates_kernel<<<dim3(32, 32), blk, SMEM_BYTES>>>(
        x, h, c,
        w_forget, w_input, w_c_dash, w_output,
        w_ip_f, w_ip_i, w_ip_c, w_ip_o,
        w_forget_c, w_input_c,
        zf, zi, zc, zo);

    lstm_ew1<<<(unsigned)(BH / 256), blk>>>(zf, zi, zc, c, ct_out, (int)BH);

    peephole_kernel<<<dim3(8, 32), blk, SMEM_BYTES>>>(ct_out, w_output_c, zo);

    lstm_ew2<<<(unsigned)(BH / 256), blk>>>(zo, ct_out, ht_out, (int)BH);

    vocab_kernel<<<dim3(250, 32), blk>>>(ht_out, w_op, out, V_);
}

// round 6
// speedup vs baseline: 1.4190x; 1.1277x over previous
#include <cuda_runtime.h>
#include <mma.h>
#include <cstdint>

using namespace nvcuda;

#define B_ 4096
#define H_ 1024
#define V_ 32000

// Scratch (device-global arrays: allocation-free per harness rules)
__device__ float g_zf[(size_t)B_ * H_];
__device__ float g_zi[(size_t)B_ * H_];
__device__ float g_zc[(size_t)B_ * H_];
__device__ float g_zo[(size_t)B_ * H_];
__device__ float g_ct[(size_t)B_ * H_];
__device__ float g_ht[(size_t)B_ * H_];

constexpr int BM = 128, BN = 128, BK = 32;
constexpr int APAD = 8, BPAD = 8;
constexpr int A_ROW = BK + APAD;          // 40 floats
constexpr int B_ROW = BN + BPAD;          // 136 floats
constexpr int A_STAGE = BM * A_ROW;       // 5120 floats
constexpr int B_STAGE = BK * B_ROW;       // 4352 floats
constexpr int SMEM_BYTES = 2 * (A_STAGE + B_STAGE) * 4;   // 75776

__device__ __forceinline__ float sigmoidf_(float x) {
    return 1.0f / (1.0f + expf(-x));
}

__device__ __forceinline__ void cp_async16(uint32_t dst, const void* src) {
    asm volatile("cp.async.cg.shared.global [%0], [%1], 16;\n" :: "r"(dst), "l"(src));
}
__device__ __forceinline__ void cp_commit() {
    asm volatile("cp.async.commit_group;\n" ::: "memory");
}
template <int N>
__device__ __forceinline__ void cp_wait() {
    asm volatile("cp.async.wait_group %0;\n" :: "n"(N) : "memory");
}

// ============ pipelined cp.async GEMM (R3-measured 448us/2-pair launch) ============
// For latency-bound launches (gates, peephole). K per pair = 1024.
// MODE: 0 = store, 1 = accumulate onto existing C.
template <int MODE, int NPAIR>
__global__ __launch_bounds__(256) void gemm_tf32(
    const float* __restrict__ A0, const float* __restrict__ W0,
    const float* __restrict__ A1, const float* __restrict__ W1,
    const float* __restrict__ A2, const float* __restrict__ W2,
    float* __restrict__ C, int N)
{
    extern __shared__ __align__(16) float smem[];
    float* As = smem;                 // [2][BM][A_ROW]
    float* Bs = smem + 2 * A_STAGE;   // [2][BK][B_ROW]

    const int tid    = threadIdx.x;
    const int wid    = tid >> 5;
    const int warp_m = wid & 3;
    const int warp_n = wid >> 2;
    const int bm     = blockIdx.y * BM;
    const int bn     = blockIdx.x * BN;

    const uint32_t sbase = (uint32_t)__cvta_generic_to_shared(smem);

    wmma::fragment<wmma::accumulator, 16, 16, 8, float> acc[2][4];
    #pragma unroll
    for (int i = 0; i < 2; i++)
        #pragma unroll
        for (int j = 0; j < 4; j++) {
            if (MODE == 1) {
                const float* cp = C + (size_t)(bm + warp_m * 32 + i * 16) * N
                                    + (bn + warp_n * 64 + j * 16);
                wmma::load_matrix_sync(acc[i][j], cp, N, wmma::mem_row_major);
            } else {
                wmma::fill_fragment(acc[i][j], 0.0f);
            }
        }

    const float* Aps[3] = {A0, A1, A2};
    const float* Wps[3] = {W0, W1, W2};
    const int NS = NPAIR * 32;

    const int ar = tid >> 3;             // 0..31
    const int ac = (tid & 7) * 4;        // 0..28
    const int br = tid >> 5;             // 0..7
    const int bc = (tid & 31) * 4;       // 0..124

    auto load_stage = [&](int buf, int s) {
        const int p  = s >> 5;
        const int k0 = (s & 31) * BK;
        const float* __restrict__ A = Aps[p];
        const float* __restrict__ W = Wps[p];
        #pragma unroll
        for (int rr = 0; rr < 4; rr++) {
            uint32_t dst = sbase + (uint32_t)(buf * A_STAGE + (ar + rr * 32) * A_ROW + ac) * 4u;
            cp_async16(dst, A + (size_t)(bm + ar + rr * 32) * 1024 + k0 + ac);
        }
        #pragma unroll
        for (int rr = 0; rr < 4; rr++) {
            uint32_t dst = sbase + (uint32_t)(2 * A_STAGE + buf * B_STAGE + (br + rr * 8) * B_ROW + bc) * 4u;
            cp_async16(dst, W + (size_t)(k0 + br + rr * 8) * N + bn + bc);
        }
    };

    load_stage(0, 0);
    cp_commit();

    #pragma unroll 1
    for (int s = 0; s < NS; s++) {
        const int buf = s & 1;
        if (s + 1 < NS) {
            load_stage(buf ^ 1, s + 1);
            cp_commit();
            cp_wait<1>();
        } else {
            cp_wait<0>();
        }
        __syncthreads();

        const float* Ab    = As + buf * A_STAGE;
        const float* Bbase = Bs + buf * B_STAGE;

        #pragma unroll
        for (int kk = 0; kk < BK; kk += 8) {
            wmma::fragment<wmma::matrix_a, 16, 16, 8, wmma::precision::tf32, wmma::row_major> af[2];
            wmma::fragment<wmma::matrix_b, 16, 16, 8, wmma::precision::tf32, wmma::row_major> bf[4];
            #pragma unroll
            for (int i = 0; i < 2; i++) {
                wmma::load_matrix_sync(af[i], Ab + (warp_m * 32 + i * 16) * A_ROW + kk, A_ROW);
                #pragma unroll
                for (int t = 0; t < af[i].num_elements; t++)
                    af[i].x[t] = wmma::__float_to_tf32(af[i].x[t]);
            }
            #pragma unroll
            for (int j = 0; j < 4; j++) {
                wmma::load_matrix_sync(bf[j], Bbase + kk * B_ROW + warp_n * 64 + j * 16, B_ROW);
                #pragma unroll
                for (int t = 0; t < bf[j].num_elements; t++)
                    bf[j].x[t] = wmma::__float_to_tf32(bf[j].x[t]);
            }
            #pragma unroll
            for (int i = 0; i < 2; i++)
                #pragma unroll
                for (int j = 0; j < 4; j++)
                    wmma::mma_sync(acc[i][j], af[i], bf[j], acc[i][j]);
        }
        __syncthreads();
    }

    #pragma unroll
    for (int i = 0; i < 2; i++)
        #pragma unroll
        for (int j = 0; j < 4; j++) {
            float* cp = C + (size_t)(bm + warp_m * 32 + i * 16) * N
                          + (bn + warp_n * 64 + j * 16);
            wmma::store_matrix_sync(cp, acc[i][j], N, wmma::mem_row_major);
        }
}

// ============ vocab GEMM: register-staged prefetch + L2-friendly wave order ============
// Yt = sigmoid(Ht @ w_op). grid (32, 250): bm fast => A stays L2-resident.
__global__ __launch_bounds__(256) void vocab_kernel(
    const float* __restrict__ A, const float* __restrict__ W,
    float* __restrict__ C, int N)
{
    __shared__ __align__(16) float As[BM][A_ROW];
    __shared__ __align__(16) float Bs[BK][B_ROW];

    const int tid    = threadIdx.x;
    const int wid    = tid >> 5;
    const int warp_m = wid & 3;
    const int warp_n = wid >> 2;
    const int bm     = blockIdx.x * BM;      // fast dim: all bm per wave
    const int bn     = blockIdx.y * BN;

    wmma::fragment<wmma::accumulator, 16, 16, 8, float> acc[2][4];
    #pragma unroll
    for (int i = 0; i < 2; i++)
        #pragma unroll
        for (int j = 0; j < 4; j++)
            wmma::fill_fragment(acc[i][j], 0.0f);

    const int ar = tid >> 3;             // 0..31
    const int ac = (tid & 7) * 4;        // 0..28
    const int br = tid >> 5;             // 0..7
    const int bc = (tid & 31) * 4;       // 0..124

    float4 ra[4], rb[4];

    auto ldg_stage = [&](int k0) {
        #pragma unroll
        for (int rr = 0; rr < 4; rr++)
            ra[rr] = *(const float4*)(A + (size_t)(bm + ar + rr * 32) * 1024 + k0 + ac);
        #pragma unroll
        for (int rr = 0; rr < 4; rr++)
            rb[rr] = *(const float4*)(W + (size_t)(k0 + br + rr * 8) * N + bn + bc);
    };

    ldg_stage(0);

    #pragma unroll 1
    for (int k0 = 0; k0 < 1024; k0 += BK) {
        // commit staged regs to smem
        #pragma unroll
        for (int rr = 0; rr < 4; rr++)
            *(float4*)&As[ar + rr * 32][ac] = ra[rr];
        #pragma unroll
        for (int rr = 0; rr < 4; rr++)
            *(float4*)&Bs[br + rr * 8][bc] = rb[rr];
        __syncthreads();

        // prefetch next stage into regs — latency overlaps compute below
        if (k0 + BK < 1024)
            ldg_stage(k0 + BK);

        #pragma unroll
        for (int kk = 0; kk < BK; kk += 8) {
            wmma::fragment<wmma::matrix_a, 16, 16, 8, wmma::precision::tf32, wmma::row_major> af[2];
            wmma::fragment<wmma::matrix_b, 16, 16, 8, wmma::precision::tf32, wmma::row_major> bf[4];
            #pragma unroll
            for (int i = 0; i < 2; i++) {
                wmma::load_matrix_sync(af[i], &As[warp_m * 32 + i * 16][kk], A_ROW);
                #pragma unroll
                for (int t = 0; t < af[i].num_elements; t++)
                    af[i].x[t] = wmma::__float_to_tf32(af[i].x[t]);
            }
            #pragma unroll
            for (int j = 0; j < 4; j++) {
                wmma::load_matrix_sync(bf[j], &Bs[kk][warp_n * 64 + j * 16], B_ROW);
                #pragma unroll
                for (int t = 0; t < bf[j].num_elements; t++)
                    bf[j].x[t] = wmma::__float_to_tf32(bf[j].x[t]);
            }
            #pragma unroll
            for (int i = 0; i < 2; i++)
                #pragma unroll
                for (int j = 0; j < 4; j++)
                    wmma::mma_sync(acc[i][j], af[i], bf[j], acc[i][j]);
        }
        __syncthreads();
    }

    #pragma unroll
    for (int i = 0; i < 2; i++)
        #pragma unroll
        for (int j = 0; j < 4; j++) {
            #pragma unroll
            for (int t = 0; t < acc[i][j].num_elements; t++)
                acc[i][j].x[t] = sigmoidf_(acc[i][j].x[t]);
            float* cp = C + (size_t)(bm + warp_m * 32 + i * 16) * N
                          + (bn + warp_n * 64 + j * 16);
            wmma::store_matrix_sync(cp, acc[i][j], N, wmma::mem_row_major);
        }
}

// ======================= elementwise =======================
__global__ void lstm_ew1(const float* __restrict__ zf, const float* __restrict__ zi,
                         const float* __restrict__ zc, const float* __restrict__ c,
                         float* __restrict__ ct, int n)
{
    int i = blockIdx.x * blockDim.x + threadIdx.x;
    if (i < n)
        ct[i] = sigmoidf_(zf[i]) * c[i] + sigmoidf_(zi[i]) * tanhf(zc[i]);
}
__global__ void lstm_ew2(const float* __restrict__ zo, const float* __restrict__ ct,
                         float* __restrict__ ht, int n)
{
    int i = blockIdx.x * blockDim.x + threadIdx.x;
    if (i < n)
        ht[i] = sigmoidf_(zo[i]) * tanhf(ct[i]);
}

extern "C" void kernel_launch(void* const* d_in, const int* in_sizes, int n_in,
                              void* d_out, int out_size)
{
    const float* x          = (const float*)d_in[0];
    const float* h          = (const float*)d_in[1];
    const float* c          = (const float*)d_in[2];
    const float* w_forget   = (const float*)d_in[3];
    const float* w_input    = (const float*)d_in[4];
    const float* w_output   = (const float*)d_in[5];
    const float* w_c_dash   = (const float*)d_in[6];
    const float* w_forget_c = (const float*)d_in[7];
    const float* w_input_c  = (const float*)d_in[8];
    const float* w_output_c = (const float*)d_in[9];
    const float* w_op       = (const float*)d_in[10];
    const float* w_ip_f     = (const float*)d_in[11];
    const float* w_ip_i     = (const float*)d_in[12];
    const float* w_ip_o     = (const float*)d_in[13];
    const float* w_ip_c     = (const float*)d_in[14];
    float* out = (float*)d_out;

    cudaFuncSetAttribute((const void*)gemm_tf32<0, 3>, cudaFuncAttributeMaxDynamicSharedMemorySize, SMEM_BYTES);
    cudaFuncSetAttribute((const void*)gemm_tf32<0, 2>, cudaFuncAttributeMaxDynamicSharedMemorySize, SMEM_BYTES);
    cudaFuncSetAttribute((const void*)gemm_tf32<1, 1>, cudaFuncAttributeMaxDynamicSharedMemorySize, SMEM_BYTES);

    float *zf, *zi, *zc, *zo, *ctbuf, *htbuf;
    cudaGetSymbolAddress((void**)&zf, g_zf);
    cudaGetSymbolAddress((void**)&zi, g_zi);
    cudaGetSymbolAddress((void**)&zc, g_zc);
    cudaGetSymbolAddress((void**)&zo, g_zo);
    cudaGetSymbolAddress((void**)&ctbuf, g_ct);
    cudaGetSymbolAddress((void**)&htbuf, g_ht);

    const size_t BV = (size_t)B_ * V_;
    const size_t BH = (size_t)B_ * H_;
    float* ht_out = ((size_t)out_size >= BV + 2 * BH) ? (out + BV)      : htbuf;
    float* ct_out = ((size_t)out_size >= BV + 2 * BH) ? (out + BV + BH) : ctbuf;

    dim3 blk(256);
    dim3 g_h(8, 32);        // gate/peephole grids
    dim3 g_v(32, 250);      // vocab: bm fast (A L2-resident), bn slow

    // Gate pre-activations — 4 separate launches (R3-measured config)
    gemm_tf32<0, 3><<<g_h, blk, SMEM_BYTES>>>(x, w_ip_f, h, w_forget, c, w_forget_c, zf, 1024);
    gemm_tf32<0, 3><<<g_h, blk, SMEM_BYTES>>>(x, w_ip_i, h, w_input,  c, w_input_c,  zi, 1024);
    gemm_tf32<0, 2><<<g_h, blk, SMEM_BYTES>>>(x, w_ip_c, h, w_c_dash, nullptr, nullptr, zc, 1024);
    gemm_tf32<0, 2><<<g_h, blk, SMEM_BYTES>>>(x, w_ip_o, h, w_output, nullptr, nullptr, zo, 1024);

    lstm_ew1<<<(unsigned)(BH / 256), blk>>>(zf, zi, zc, c, ct_out, (int)BH);

    // zo += Ct @ w_output_c
    gemm_tf32<1, 1><<<g_h, blk, SMEM_BYTES>>>(ct_out, w_output_c, nullptr, nullptr, nullptr, nullptr,
                                              zo, 1024);

    lstm_ew2<<<(unsigned)(BH / 256), blk>>>(zo, ct_out, ht_out, (int)BH);

    // Yt = sigmoid(Ht @ w_op)
    vocab_kernel<<<g_v, blk>>>(ht_out, w_op, out, V_);
}